// round 11
// baseline (speedup 1.0000x reference)
#include <cuda_runtime.h>
#include <cstdint>

#define NSESS    4096
#define NTRIALS  2048
#define NWORDS   (NTRIALS / 32)        // 64 packed words per session

// filter chunking
#define FCHUNK   32                    // output trials per warp (1 packed word)
#define FNCHUNK  (NTRIALS / FCHUNK)    // 64 chunks
#define FWARM    16                    // warmup trials (validated: rel_err ~6e-5)

// pipeline split (session groups)
#define NSPLIT   4
#define SGRP     (NSESS / NSPLIT)      // 1024 sessions per group

// packed bits: bit i of packed[w*NSESS+s] = (chose_left==outcome) at trial w*32+i
__device__ uint32_t g_packed[NWORDS * NSESS];

__device__ __forceinline__ float frcp_fast(float x) {
    float y;
    asm("rcp.approx.f32 %0, %1;" : "=f"(y) : "f"(x));
    return y;
}

// ---------------------------------------------------------------------------
// Kernel 1: pack (R5/R10-proven). One warp per QUARTER-session of one group.
// ---------------------------------------------------------------------------
__global__ void __launch_bounds__(128)
pack_kernel(const float* __restrict__ in, uint32_t* __restrict__ packed,
            int sess_base) {
    const int lane  = threadIdx.x & 31;
    const int gwarp = blockIdx.x * 4 + (threadIdx.x >> 5);
    const int s     = sess_base + (gwarp >> 2);
    const int quart = gwarp & 3;

    const float* srow = in + (long)s * (NTRIALS * 3) + quart * (512 * 3);

#pragma unroll
    for (int it = 0; it < 4; it++) {
        const float4* p = (const float4*)(srow + it * 384) + 3 * lane;
        float4 x0 = p[0];   // cl0 cr0 o0  cl1
        float4 x1 = p[1];   // cr1 o1  cl2 cr2
        float4 x2 = p[2];   // o2  cl3 cr3 o3

        int b0 = (x0.x == x0.z);
        int b1 = (x0.w == x1.y);
        int b2 = (x1.z == x2.x);
        int b3 = (x2.y == x2.w);
        uint32_t nib = (uint32_t)(b0 | (b1 << 1) | (b2 << 2) | (b3 << 3));
        uint32_t v = nib << ((lane & 7) * 4);
        v |= __shfl_xor_sync(0xFFFFFFFFu, v, 1);
        v |= __shfl_xor_sync(0xFFFFFFFFu, v, 2);
        v |= __shfl_xor_sync(0xFFFFFFFFu, v, 4);
        if ((lane & 7) == 0) {
            int w = quart * 16 + it * 4 + (lane >> 3);
            packed[w * NSESS + s] = v;
        }
    }
}

// ---------------------------------------------------------------------------
// Kernel 2: filter (R10-proven homogeneous recurrence), per session group.
// ---------------------------------------------------------------------------
#define ROW_F4 9
#define WARP_F4 (32 * ROW_F4)

__global__ void __launch_bounds__(128)
filter_kernel(const uint32_t* __restrict__ packed,
              const float* __restrict__ p_stay_raw,
              const float* __restrict__ c_raw,
              float* __restrict__ out,
              int sess_base) {
    __shared__ float4 stage4[4 * WARP_F4];
    __shared__ float4 klut[2];

    const int lane  = threadIdx.x & 31;
    const int wid   = threadIdx.x >> 5;
    const int gwarp = blockIdx.x * 4 + wid;
    const int chunk = gwarp & (FNCHUNK - 1);
    const int sess0 = sess_base + (gwarp >> 6) * 32;   // FNCHUNK == 64

    const float p  = 1.0f / (1.0f + __expf(-p_stay_raw[0]));
    const float c  = 1.0f / (1.0f + __expf(-c_raw[0]));
    const float A  = 0.5f * (1.0f + c);
    const float B  = 0.5f * (1.0f - c);
    const float q  = 0.5f * (1.0f + p);
    const float qm = 0.5f * (1.0f - p);

    if (threadIdx.x < 2) {
        float e0 = threadIdx.x ? A : B;
        float e1 = 1.0f - e0;
        klut[threadIdx.x] = make_float4(q * e0, qm * e1, qm * e0, q * e1);
    }
    __syncthreads();

    const uint32_t wcur = packed[chunk * NSESS + sess0 + lane];
    const uint32_t wprev = (chunk > 0)
        ? packed[(chunk - 1) * NSESS + sess0 + lane] : 0u;

    float4* ws4 = stage4 + wid * WARP_F4;
    float4* ob4 = ws4 + lane * ROW_F4;

    float v0 = 0.5f, v1 = 0.5f;

    if (chunk > 0) {
#pragma unroll
        for (int i = 0; i < FWARM; i++) {
            float4 K = klut[(wprev >> (16 + i)) & 1u];
            float a = fmaf(K.x, v0, K.y * v1);
            float b = fmaf(K.z, v0, K.w * v1);
            v0 = a; v1 = b;
        }
        float r = frcp_fast(v0 + v1);
        v0 *= r; v1 *= r;
    }

#pragma unroll
    for (int h = 0; h < 2; h++) {
        float r_mid = 1.0f;
        float pa = 0.0f, pb = 0.0f;
#pragma unroll
        for (int i = 0; i < 16; i++) {
            float4 K = klut[(wcur >> (h * 16 + i)) & 1u];
            float a = fmaf(K.x, v0, K.y * v1);
            float b = fmaf(K.z, v0, K.w * v1);
            float r = frcp_fast(a + b);
            if (i & 1) {
                ob4[i >> 1] = make_float4(pa, pb, a * r, b * r);
            } else {
                pa = a * r; pb = b * r;
            }
            if (i == 7) r_mid = r;
            v0 = a; v1 = b;
        }
        v0 *= r_mid; v1 *= r_mid;

        __syncwarp();
        const int T = chunk * 32 + h * 16;
        float4* og4 = (float4*)out + (long)sess0 * (NTRIALS / 2) + (T >> 1);
#pragma unroll
        for (int j = 0; j < 8; j++) {
            int idx = j * 32 + lane;
            int row = idx >> 3;
            int col = idx & 7;
            og4[(long)row * (NTRIALS / 2) + col] = ws4[row * ROW_F4 + col];
        }
        __syncwarp();
    }
}

// ---------------------------------------------------------------------------
// Launch: 2-stage session-pipelined graph.
//   main(0): P0, F0, F1, F2, F3       s2: P1, P2, P3
//   F_i gated on P_i via events; s2 forked from main after P0, joined via eP3.
// Streams/events created per call (host-side objects; no device allocations,
// no static caching). Falls back to serial if stream creation fails.
// ---------------------------------------------------------------------------
extern "C" void kernel_launch(void* const* d_in, const int* in_sizes, int n_in,
                              void* d_out, int out_size) {
    const float* in   = (const float*)d_in[0];
    const float* praw = (const float*)d_in[1];
    const float* craw = (const float*)d_in[2];
    float* out = (float*)d_out;

    uint32_t* packed = nullptr;
    cudaGetSymbolAddress((void**)&packed, g_packed);

    const int PACK_BLKS = SGRP;                         // 1024 blocks/group
    const int FILT_BLKS = (SGRP / 32) * FNCHUNK / 4;    // 512 blocks/group

    cudaStream_t s2 = nullptr;
    bool forked = (cudaStreamCreateWithFlags(&s2, cudaStreamNonBlocking)
                   == cudaSuccess);

    if (!forked) {
        // serial fallback (== R10 behavior)
        for (int g = 0; g < NSPLIT; g++)
            pack_kernel<<<PACK_BLKS, 128>>>(in, packed, g * SGRP);
        for (int g = 0; g < NSPLIT; g++)
            filter_kernel<<<FILT_BLKS, 128>>>(packed, praw, craw, out, g * SGRP);
        return;
    }

    cudaEvent_t eP[NSPLIT];
    for (int g = 0; g < NSPLIT; g++)
        cudaEventCreateWithFlags(&eP[g], cudaEventDisableTiming);

    // P0 on main stream
    pack_kernel<<<PACK_BLKS, 128>>>(in, packed, 0);
    cudaEventRecord(eP[0], 0);

    // fork s2 after P0; run P1..P3 there
    cudaStreamWaitEvent(s2, eP[0], 0);
    for (int g = 1; g < NSPLIT; g++) {
        pack_kernel<<<PACK_BLKS, 128, 0, s2>>>(in, packed, g * SGRP);
        cudaEventRecord(eP[g], s2);
    }

    // filters on main, each gated on its pack group (F0's gate already on main)
    filter_kernel<<<FILT_BLKS, 128>>>(packed, praw, craw, out, 0);
    for (int g = 1; g < NSPLIT; g++) {
        cudaStreamWaitEvent(0, eP[g], 0);
        filter_kernel<<<FILT_BLKS, 128>>>(packed, praw, craw, out, g * SGRP);
    }
    // s2 fully joined into main via the eP[3] wait above.
}

// round 12
// speedup vs baseline: 1.2664x; 1.2664x over previous
#include <cuda_runtime.h>
#include <cstdint>

#define NSESS    4096
#define NTRIALS  2048
#define NWORDS   (NTRIALS / 32)        // 64 packed words per session

// filter chunking
#define FCHUNK   32                    // output trials per warp (1 packed word)
#define FNCHUNK  (NTRIALS / FCHUNK)    // 64 chunks
#define FWARM    16                    // warmup trials (validated: rel_err ~6e-5)

// packed bits: bit i of packed[w*NSESS+s] = (chose_left==outcome) at trial w*32+i
__device__ uint32_t g_packed[NWORDS * NSESS];

__device__ __forceinline__ float frcp_fast(float x) {
    float y;
    asm("rcp.approx.f32 %0, %1;" : "=f"(y) : "f"(x));
    return y;
}

// ---------------------------------------------------------------------------
// Kernel 1: pack (R10-proven, untouched). One warp per QUARTER-session;
// 4 iters x 3 LDG.128, nibble + shuffle assembly.
// ---------------------------------------------------------------------------
__global__ void __launch_bounds__(128)
pack_kernel(const float* __restrict__ in, uint32_t* __restrict__ packed) {
    const int lane  = threadIdx.x & 31;
    const int gwarp = blockIdx.x * 4 + (threadIdx.x >> 5);
    const int s     = gwarp >> 2;
    const int quart = gwarp & 3;

    const float* srow = in + (long)s * (NTRIALS * 3) + quart * (512 * 3);

#pragma unroll
    for (int it = 0; it < 4; it++) {
        const float4* p = (const float4*)(srow + it * 384) + 3 * lane;
        float4 x0 = p[0];   // cl0 cr0 o0  cl1
        float4 x1 = p[1];   // cr1 o1  cl2 cr2
        float4 x2 = p[2];   // o2  cl3 cr3 o3

        int b0 = (x0.x == x0.z);
        int b1 = (x0.w == x1.y);
        int b2 = (x1.z == x2.x);
        int b3 = (x2.y == x2.w);
        uint32_t nib = (uint32_t)(b0 | (b1 << 1) | (b2 << 2) | (b3 << 3));
        uint32_t v = nib << ((lane & 7) * 4);
        v |= __shfl_xor_sync(0xFFFFFFFFu, v, 1);
        v |= __shfl_xor_sync(0xFFFFFFFFu, v, 2);
        v |= __shfl_xor_sync(0xFFFFFFFFu, v, 4);
        if ((lane & 7) == 0) {
            int w = quart * 16 + it * 4 + (lane >> 3);
            packed[w * NSESS + s] = v;
        }
    }
}

// ---------------------------------------------------------------------------
// Kernel 2: filter, ALU-coefficient form (no klut LDS).
//   e0 = bit ? A : B ; u0 = e0*v0 ; u1 = (1-e0)*v1 ; s = u0+u1
//   a  = q*u0 + qm*u1 ; b = s - a  (exact, since q+qm = 1)
//   out = (x, 1-x) with x = a * rcp(s)
// One warp = 32 sessions x one 32-trial chunk (+16 warmup). 8192 warps.
// ---------------------------------------------------------------------------
#define ROW_F4 9
#define WARP_F4 (32 * ROW_F4)

__global__ void __launch_bounds__(128, 10)
filter_kernel(const uint32_t* __restrict__ packed,
              const float* __restrict__ p_stay_raw,
              const float* __restrict__ c_raw,
              float* __restrict__ out) {
    __shared__ float4 stage4[4 * WARP_F4];   // 18432 B

    const int lane  = threadIdx.x & 31;
    const int wid   = threadIdx.x >> 5;
    const int gwarp = blockIdx.x * 4 + wid;
    const int chunk = gwarp & (FNCHUNK - 1);
    const int sess0 = (gwarp >> 6) * 32;     // FNCHUNK == 64

    // packed words first: overlap their DRAM latency with parameter math
    const uint32_t wcur = packed[chunk * NSESS + sess0 + lane];
    const uint32_t wprev = (chunk > 0)
        ? packed[(chunk - 1) * NSESS + sess0 + lane] : 0u;

    // model constants
    const float pv = 1.0f / (1.0f + __expf(-p_stay_raw[0]));
    const float cv = 1.0f / (1.0f + __expf(-c_raw[0]));
    const float A  = 0.5f * (1.0f + cv);
    const float B  = 0.5f * (1.0f - cv);
    const float q  = 0.5f * (1.0f + pv);
    const float qm = 0.5f * (1.0f - pv);

    float4* ws4 = stage4 + wid * WARP_F4;
    float4* ob4 = ws4 + lane * ROW_F4;

    float v0 = 0.5f, v1 = 0.5f;

    // ---- warmup: high 16 bits of previous word, renorm once ----
    if (chunk > 0) {
#pragma unroll
        for (int i = 0; i < FWARM; i++) {
            float e0 = ((wprev >> (16 + i)) & 1u) ? A : B;
            float u0 = e0 * v0;
            float u1 = fmaf(-e0, v1, v1);
            float s  = u0 + u1;
            float a  = fmaf(q, u0, qm * u1);
            v0 = a;
            v1 = s - a;
        }
        float r = frcp_fast(v0 + v1);
        v0 *= r; v1 *= r;
    }

    // ---- output: 2 halves of 16 trials, staged + coalesced flush ----
#pragma unroll
    for (int h = 0; h < 2; h++) {
        float r_mid = 1.0f;
        float px = 0.0f;
#pragma unroll
        for (int i = 0; i < 16; i++) {
            float e0 = ((wcur >> (h * 16 + i)) & 1u) ? A : B;
            float u0 = e0 * v0;
            float u1 = fmaf(-e0, v1, v1);
            float s  = u0 + u1;
            float a  = fmaf(q, u0, qm * u1);
            float r  = frcp_fast(s);       // off-chain: feeds outputs only
            float x  = a * r;
            if (i & 1) {
                ob4[i >> 1] = make_float4(px, 1.0f - px, x, 1.0f - x);
            } else {
                px = x;
            }
            if (i == 7) r_mid = r;
            v0 = a;
            v1 = s - a;
        }
        v0 *= r_mid; v1 *= r_mid;          // keep magnitudes in range

        __syncwarp();
        const int T = chunk * 32 + h * 16;
        float4* og4 = (float4*)out + (long)sess0 * (NTRIALS / 2) + (T >> 1);
        // 32 rows x 8 float4 per half; 8 lanes per 128B row segment
#pragma unroll
        for (int j = 0; j < 8; j++) {
            int idx = j * 32 + lane;
            int row = idx >> 3;
            int col = idx & 7;
            og4[(long)row * (NTRIALS / 2) + col] = ws4[row * ROW_F4 + col];
        }
        __syncwarp();
    }
}

extern "C" void kernel_launch(void* const* d_in, const int* in_sizes, int n_in,
                              void* d_out, int out_size) {
    const float* in   = (const float*)d_in[0];
    const float* praw = (const float*)d_in[1];
    const float* craw = (const float*)d_in[2];
    float* out = (float*)d_out;

    uint32_t* packed = nullptr;
    cudaGetSymbolAddress((void**)&packed, g_packed);

    pack_kernel<<<NSESS, 128>>>(in, packed);                                     // 16384 warps
    filter_kernel<<<(NSESS / 32) * FNCHUNK / 4, 128>>>(packed, praw, craw, out); // 8192 warps
}

// round 13
// speedup vs baseline: 1.2883x; 1.0173x over previous
#include <cuda_runtime.h>
#include <cstdint>

#define NSESS    4096
#define NTRIALS  2048
#define NWORDS   (NTRIALS / 32)        // 64 packed words per session

// filter chunking
#define FCHUNK   32                    // output trials per warp (1 packed word)
#define FNCHUNK  (NTRIALS / FCHUNK)    // 64 chunks
#define FWARM    16                    // warmup trials (validated: rel_err ~6e-5)

// packed bits: bit i of packed[w*NSESS+s] = (chose_left==outcome) at trial w*32+i
__device__ uint32_t g_packed[NWORDS * NSESS];

__device__ __forceinline__ float frcp_fast(float x) {
    float y;
    asm("rcp.approx.f32 %0, %1;" : "=f"(y) : "f"(x));
    return y;
}

__device__ __forceinline__ void cp_async16(uint32_t dst, const void* src) {
    asm volatile("cp.async.cg.shared.global [%0], [%1], 16;\n" :: "r"(dst), "l"(src));
}
__device__ __forceinline__ void cp_commit() {
    asm volatile("cp.async.commit_group;\n" ::: "memory");
}
__device__ __forceinline__ void cp_wait1() {
    asm volatile("cp.async.wait_group 1;\n" ::: "memory");
}
__device__ __forceinline__ void cp_wait0() {
    asm volatile("cp.async.wait_group 0;\n" ::: "memory");
}

// ---------------------------------------------------------------------------
// Kernel 1: pack v4. One warp per QUARTER-session (512 trials = 4 tiles of
// 128 trials / 1536 B). Each tile staged via 3 perfectly-coalesced cp.async
// rounds (512 B contiguous per round), double-buffered; lanes read back 48 B
// via 3 conflict-free LDS.128; R5-proven nibble+shuffle word assembly.
// ---------------------------------------------------------------------------
#define PTILE 1536

__global__ void __launch_bounds__(128)
pack_kernel(const float* __restrict__ in, uint32_t* __restrict__ packed) {
    __shared__ __align__(16) char buf[4][2][PTILE];   // 12288 B

    const int lane  = threadIdx.x & 31;
    const int wid   = threadIdx.x >> 5;
    const int gwarp = blockIdx.x * 4 + wid;
    const int s     = gwarp >> 2;
    const int quart = gwarp & 3;

    const char* src = (const char*)in + (long)s * (NTRIALS * 12) + quart * (512 * 12);
    const uint32_t sbase = (uint32_t)__cvta_generic_to_shared(&buf[wid][0][0]);

    // prologue: stage tile 0
#pragma unroll
    for (int r = 0; r < 3; r++)
        cp_async16(sbase + r * 512 + lane * 16, src + r * 512 + lane * 16);
    cp_commit();

#pragma unroll
    for (int t = 0; t < 4; t++) {
        if (t < 3) {
            const char* nsrc = src + (t + 1) * PTILE;
            const uint32_t ndst = sbase + ((t + 1) & 1) * PTILE;
#pragma unroll
            for (int r = 0; r < 3; r++)
                cp_async16(ndst + r * 512 + lane * 16, nsrc + r * 512 + lane * 16);
            cp_commit();
            cp_wait1();
        } else {
            cp_wait0();
        }
        __syncwarp();

        const float4* rp = (const float4*)(&buf[wid][t & 1][0] + 48 * lane);
        float4 x0 = rp[0];   // cl0 cr0 o0  cl1
        float4 x1 = rp[1];   // cr1 o1  cl2 cr2
        float4 x2 = rp[2];   // o2  cl3 cr3 o3

        int b0 = (x0.x == x0.z);
        int b1 = (x0.w == x1.y);
        int b2 = (x1.z == x2.x);
        int b3 = (x2.y == x2.w);
        uint32_t nib = (uint32_t)(b0 | (b1 << 1) | (b2 << 2) | (b3 << 3));
        uint32_t v = nib << ((lane & 7) * 4);
        v |= __shfl_xor_sync(0xFFFFFFFFu, v, 1);
        v |= __shfl_xor_sync(0xFFFFFFFFu, v, 2);
        v |= __shfl_xor_sync(0xFFFFFFFFu, v, 4);
        if ((lane & 7) == 0) {
            int w = quart * 16 + t * 4 + (lane >> 3);
            packed[w * NSESS + s] = v;
        }
        __syncwarp();
    }
}

// ---------------------------------------------------------------------------
// Kernel 2: filter (R12-proven, untouched). ALU-coefficient form, no klut LDS.
// ---------------------------------------------------------------------------
#define ROW_F4 9
#define WARP_F4 (32 * ROW_F4)

__global__ void __launch_bounds__(128, 10)
filter_kernel(const uint32_t* __restrict__ packed,
              const float* __restrict__ p_stay_raw,
              const float* __restrict__ c_raw,
              float* __restrict__ out) {
    __shared__ float4 stage4[4 * WARP_F4];   // 18432 B

    const int lane  = threadIdx.x & 31;
    const int wid   = threadIdx.x >> 5;
    const int gwarp = blockIdx.x * 4 + wid;
    const int chunk = gwarp & (FNCHUNK - 1);
    const int sess0 = (gwarp >> 6) * 32;     // FNCHUNK == 64

    const uint32_t wcur = packed[chunk * NSESS + sess0 + lane];
    const uint32_t wprev = (chunk > 0)
        ? packed[(chunk - 1) * NSESS + sess0 + lane] : 0u;

    const float pv = 1.0f / (1.0f + __expf(-p_stay_raw[0]));
    const float cv = 1.0f / (1.0f + __expf(-c_raw[0]));
    const float A  = 0.5f * (1.0f + cv);
    const float B  = 0.5f * (1.0f - cv);
    const float q  = 0.5f * (1.0f + pv);
    const float qm = 0.5f * (1.0f - pv);

    float4* ws4 = stage4 + wid * WARP_F4;
    float4* ob4 = ws4 + lane * ROW_F4;

    float v0 = 0.5f, v1 = 0.5f;

    if (chunk > 0) {
#pragma unroll
        for (int i = 0; i < FWARM; i++) {
            float e0 = ((wprev >> (16 + i)) & 1u) ? A : B;
            float u0 = e0 * v0;
            float u1 = fmaf(-e0, v1, v1);
            float s  = u0 + u1;
            float a  = fmaf(q, u0, qm * u1);
            v0 = a;
            v1 = s - a;
        }
        float r = frcp_fast(v0 + v1);
        v0 *= r; v1 *= r;
    }

#pragma unroll
    for (int h = 0; h < 2; h++) {
        float r_mid = 1.0f;
        float px = 0.0f;
#pragma unroll
        for (int i = 0; i < 16; i++) {
            float e0 = ((wcur >> (h * 16 + i)) & 1u) ? A : B;
            float u0 = e0 * v0;
            float u1 = fmaf(-e0, v1, v1);
            float s  = u0 + u1;
            float a  = fmaf(q, u0, qm * u1);
            float r  = frcp_fast(s);
            float x  = a * r;
            if (i & 1) {
                ob4[i >> 1] = make_float4(px, 1.0f - px, x, 1.0f - x);
            } else {
                px = x;
            }
            if (i == 7) r_mid = r;
            v0 = a;
            v1 = s - a;
        }
        v0 *= r_mid; v1 *= r_mid;

        __syncwarp();
        const int T = chunk * 32 + h * 16;
        float4* og4 = (float4*)out + (long)sess0 * (NTRIALS / 2) + (T >> 1);
#pragma unroll
        for (int j = 0; j < 8; j++) {
            int idx = j * 32 + lane;
            int row = idx >> 3;
            int col = idx & 7;
            og4[(long)row * (NTRIALS / 2) + col] = ws4[row * ROW_F4 + col];
        }
        __syncwarp();
    }
}

extern "C" void kernel_launch(void* const* d_in, const int* in_sizes, int n_in,
                              void* d_out, int out_size) {
    const float* in   = (const float*)d_in[0];
    const float* praw = (const float*)d_in[1];
    const float* craw = (const float*)d_in[2];
    float* out = (float*)d_out;

    uint32_t* packed = nullptr;
    cudaGetSymbolAddress((void**)&packed, g_packed);

    pack_kernel<<<NSESS, 128>>>(in, packed);                                     // 16384 warps
    filter_kernel<<<(NSESS / 32) * FNCHUNK / 4, 128>>>(packed, praw, craw, out); // 8192 warps
}